// round 13
// baseline (speedup 1.0000x reference)
#include <cuda_runtime.h>
#include <cuda_fp16.h>
#include <cstdint>
#include <cstddef>

#define Bv     8
#define Nv     128
#define FNv    64

// ------------------------------ helpers ------------------------------
__device__ __forceinline__ uint32_t smem_u32(const void* p) {
    uint32_t a;
    asm("{ .reg .u64 t; cvta.to.shared.u64 t, %1; cvt.u32.u64 %0, t; }" : "=r"(a) : "l"(p));
    return a;
}
__device__ __forceinline__ void cp16(uint32_t dst, const void* src) {
    asm volatile("cp.async.cg.shared.global [%0], [%1], 16;" :: "r"(dst), "l"(src) : "memory");
}
__device__ __forceinline__ void cp_commit() {
    asm volatile("cp.async.commit_group;" ::: "memory");
}
template <int N>
__device__ __forceinline__ void cp_wait() {
    asm volatile("cp.async.wait_group %0;" :: "n"(N) : "memory");
}
__device__ __forceinline__ uint32_t packh2(float lo, float hi) {
    uint32_t d; asm("cvt.rn.f16x2.f32 %0, %1, %2;" : "=r"(d) : "f"(hi), "f"(lo)); return d;
}
__device__ __forceinline__ void mma16(float* c, const uint32_t* a, uint32_t b0, uint32_t b1) {
    asm volatile(
        "mma.sync.aligned.m16n8k16.row.col.f32.f16.f16.f32 "
        "{%0,%1,%2,%3}, {%4,%5,%6,%7}, {%8,%9}, {%0,%1,%2,%3};"
        : "+f"(c[0]), "+f"(c[1]), "+f"(c[2]), "+f"(c[3])
        : "r"(a[0]), "r"(a[1]), "r"(a[2]), "r"(a[3]), "r"(b0), "r"(b1));
}
__device__ __forceinline__ double pack2d(float x, float y) {
    double r; asm("mov.b64 %0, {%1, %2};" : "=d"(r) : "f"(x), "f"(y)); return r;
}
__device__ __forceinline__ double add2(double a, double b) {
    double r; asm("add.rn.f32x2 %0, %1, %2;" : "=d"(r) : "d"(a), "d"(b)); return r;
}
__device__ __forceinline__ double fma2v(double a, double b, double c) {
    double r; asm("fma.rn.f32x2 %0, %1, %2, %3;" : "=d"(r) : "d"(a), "d"(b), "d"(c)); return r;
}
__device__ __forceinline__ float2 unpack2d(double v) {
    float2 f; asm("mov.b64 {%0, %1}, %2;" : "=f"(f.x), "=f"(f.y) : "d"(v)); return f;
}

// ------------------------------ main kernel ------------------------------
// CTA = (b, j-block of 8). 256 threads, 8 warps: wm = wid&3 (32 tile rows),
// wn = wid>>2 (64 n-cols = 32 l). Tile row r = il*8 + jl, i = ii*16+il, j = jb*8+jl.
// W smem: [n=2l+br (128)][kp halves (192 perm + pad16)] rows of 208 halves (104 words).
// ks 0..3 = We (W rows 128..191), ks 4..7 = Wj (64..127), ks 8..11 = Wi (0..63).
#define WROWH   208
#define OFF_W   0            // 128 x 416 B = 53248
#define OFF_E16 53248        // 2 x 20480 = 40960
#define E16BUF  20480
#define OFF_PI  94208        // 128 i x 66 float2 = 67584
#define PIW     66
#define OFF_PJ  161792       // 8 j x 66 float2 = 4224
#define PJW     66
#define OFF_A   166016       // 128 i x 8 j fp32 = 4096
#define OFF_BS  170112       // 64 float2 (pre-halved) = 512
#define SMEM_DYN 170624

__global__ void __launch_bounds__(256, 1)
main_kernel(const float* __restrict__ A,
            const float* __restrict__ E,
            const float* __restrict__ H,
            const float* __restrict__ Watt,
            const float* __restrict__ Wnei,
            const float* __restrict__ biasA,
            const float* __restrict__ biasN,
            float* __restrict__ out) {
    extern __shared__ char sm[];
    const uint32_t sb = smem_u32(sm);

    const int t = threadIdx.x, lane = t & 31, wid = t >> 5;
    const int g = lane >> 2, tg = lane & 3;
    const int b = blockIdx.x >> 4, jb = blockIdx.x & 15;
    const int wm = wid & 3;                     // m-quadrant
    const int wn = wid >> 2;                    // l-half
    const int mbase = wm * 32;
    const int lbase = wn * 32;
    const int nrow0 = wn * 64;

    const uint32_t* __restrict__ Ws = (const uint32_t*)(sm + OFF_W);

    // ---- A block via cp.async ----
    {
        const int ia = t >> 1, ha = t & 1;
        cp16(sb + OFF_A + ia * 32 + ha * 16,
             (const char*)(A + ((size_t)(b * Nv + ia)) * Nv + jb * 8) + ha * 16);
        cp_commit();
    }

    // ---- W gather: coalesced fp32 LDG -> permuted fp16 STS (inline prep) ----
    {
        unsigned short* __restrict__ Wh = (unsigned short*)(sm + OFF_W);
        #pragma unroll
        for (int v = 0; v < 24; v++) {
            const int gid4 = v * 256 + t;            // < 6144
            const int br = gid4 / 3072, rem = gid4 % 3072;
            const int row = rem >> 4, l4 = (rem & 15) * 4;
            const float* __restrict__ W = br ? Wnei : Watt;
            const float4 w4 = __ldg((const float4*)(W + row * 64 + l4));
            int ks;
            if (row >= 128)     ks = (row - 128) >> 4;
            else if (row >= 64) ks = row >> 4;
            else                ks = 8 + (row >> 4);
            const int k16 = row & 15;
            const int p16 = ((k16 >> 2) & 1) * 8 + ((k16 >> 1) & 1) * 4
                          + ((k16 >> 3) & 1) * 2 + (k16 & 1);
            const int kp = ks * 16 + p16;
            const float wv[4] = {w4.x, w4.y, w4.z, w4.w};
            #pragma unroll
            for (int q = 0; q < 4; q++) {
                const int n = 2 * (l4 + q) + br;
                Wh[n * WROWH + kp] = __half_as_ushort(__float2half_rn(wv[q]));
            }
        }
    }

    // ---- H tile: LDG -> fp16 permuted STS into E16 buf0 ----
    {
        const float4* Hg = (const float4*)(H + (size_t)b * Nv * FNv);
        float4 hl[8];
        #pragma unroll
        for (int v = 0; v < 8; v++) hl[v] = Hg[v * 256 + t];
        uint32_t* Ebw = (uint32_t*)(sm + OFF_E16);
        #pragma unroll
        for (int v = 0; v < 8; v++) {
            const int n = v * 256 + t, row = n >> 4, kgf = n & 15;
            const int wbase = row * 40 + (kgf >> 2) * 8 + ((kgf & 1) * 4) + ((kgf >> 1) & 1);
            Ebw[wbase]     = packh2(hl[v].x, hl[v].y);
            Ebw[wbase + 2] = packh2(hl[v].z, hl[v].w);
        }
    }
    if (t < 64)
        ((float2*)(sm + OFF_BS))[t] =
            make_float2(0.5f * __ldg(biasA + t), 0.5f * __ldg(biasN + t));
    cp_wait<0>();
    __syncthreads();          // W + A + H-tile resident

    // ---- prologue GEMM: Pi (ks 8..11, all 128 nodes) and Pj (ks 4..7, 8 nodes) ----
    {
        const uint32_t* __restrict__ Ew = (const uint32_t*)(sm + OFF_E16);
        float cpj[2][8][4], cpi[2][8][4];
        #pragma unroll
        for (int mt = 0; mt < 2; mt++)
            #pragma unroll
            for (int nt = 0; nt < 8; nt++)
                #pragma unroll
                for (int q = 0; q < 4; q++) { cpj[mt][nt][q] = 0.f; cpi[mt][nt][q] = 0.f; }

        #pragma unroll
        for (int ks = 0; ks < 4; ks++) {
            uint32_t a[2][4];
            #pragma unroll
            for (int mt = 0; mt < 2; mt++) {
                const int r = mbase + mt * 16 + g;
                const uint2 u0 = *(const uint2*)(Ew + r * 40 + ks * 8 + tg * 2);
                const uint2 u1 = *(const uint2*)(Ew + (r + 8) * 40 + ks * 8 + tg * 2);
                a[mt][0] = u0.x; a[mt][1] = u1.x; a[mt][2] = u0.y; a[mt][3] = u1.y;
            }
            #pragma unroll
            for (int nt = 0; nt < 8; nt++) {
                const int nr = (nrow0 + nt * 8 + g) * 104;
                const uint2 bj = *(const uint2*)(Ws + nr + (ks + 4) * 8 + tg * 2);
                const uint2 bi = *(const uint2*)(Ws + nr + (ks + 8) * 8 + tg * 2);
                mma16(cpj[0][nt], a[0], bj.x, bj.y);
                mma16(cpj[1][nt], a[1], bj.x, bj.y);
                mma16(cpi[0][nt], a[0], bi.x, bi.y);
                mma16(cpi[1][nt], a[1], bi.x, bi.y);
            }
        }
        // scatter Pi (all 128 rows)
        float2* __restrict__ PIs = (float2*)(sm + OFF_PI);
        #pragma unroll
        for (int mt = 0; mt < 2; mt++) {
            const int r0 = mbase + mt * 16 + g;
            #pragma unroll
            for (int nt = 0; nt < 8; nt++) {
                const int l = lbase + nt * 4 + tg;
                PIs[(size_t)r0 * PIW + l]       = make_float2(cpi[mt][nt][0], cpi[mt][nt][1]);
                PIs[(size_t)(r0 + 8) * PIW + l] = make_float2(cpi[mt][nt][2], cpi[mt][nt][3]);
            }
        }
        // scatter Pj window (rows jb*8 .. +8): owning (wm, mt, h) combo
        float2* __restrict__ PJs = (float2*)(sm + OFF_PJ);
        #pragma unroll
        for (int mt = 0; mt < 2; mt++) {
            #pragma unroll
            for (int h = 0; h < 2; h++) {
                if (wm * 4 + mt * 2 + h == jb) {
                    #pragma unroll
                    for (int nt = 0; nt < 8; nt++) {
                        const int l = lbase + nt * 4 + tg;
                        const float va = cpj[mt][nt][h * 2];
                        const float vn = cpj[mt][nt][h * 2 + 1];
                        PJs[(size_t)g * PJW + l] = make_float2(va, vn);
                    }
                }
            }
        }
    }

    // ---- hoist B fragments (We, ks 0..3) into registers ----
    uint2 Breg[4][8];
    #pragma unroll
    for (int ks = 0; ks < 4; ks++)
        #pragma unroll
        for (int nt = 0; nt < 8; nt++)
            Breg[ks][nt] = *(const uint2*)(Ws + (nrow0 + nt * 8 + g) * 104 + ks * 8 + tg * 2);

    // ---- prefetch E tile 0 (rows r = il*8+jl, i = r>>3, j = jb*8 + (r&7)) ----
    float4 el[8];
    {
        #pragma unroll
        for (int v = 0; v < 8; v++) {
            const int n = v * 256 + t, row = n >> 4, kgf = n & 15;
            el[v] = __ldg((const float4*)
                (E + (((size_t)(b * Nv + (row >> 3)) * Nv) + jb * 8 + (row & 7)) * FNv) + kgf);
        }
    }
    __syncthreads();          // Pi/Pj visible; H reads done -> buf0 reusable

    // ---- Pj into registers (j = jb*8+g fixed per thread) ----
    double pj2[8];
    {
        const double* __restrict__ PJd = (const double*)(sm + OFF_PJ);
        #pragma unroll
        for (int nt = 0; nt < 8; nt++)
            pj2[nt] = PJd[(size_t)g * PJW + lbase + nt * 4 + tg];
    }

    float outacc[8];
    #pragma unroll
    for (int nt = 0; nt < 8; nt++) outacc[nt] = 0.f;

    for (int ii = 0; ii < 8; ii++) {
        // ---- convert + store tile ii ----
        {
            uint32_t* Ebw = (uint32_t*)(sm + OFF_E16 + (ii & 1) * E16BUF);
            #pragma unroll
            for (int v = 0; v < 8; v++) {
                const int n = v * 256 + t, row = n >> 4, kgf = n & 15;
                const int wbase = row * 40 + (kgf >> 2) * 8 + ((kgf & 1) * 4) + ((kgf >> 1) & 1);
                Ebw[wbase]     = packh2(el[v].x, el[v].y);
                Ebw[wbase + 2] = packh2(el[v].z, el[v].w);
            }
        }
        __syncthreads();

        // ---- prefetch tile ii+1 ----
        if (ii + 1 < 8) {
            #pragma unroll
            for (int v = 0; v < 8; v++) {
                const int n = v * 256 + t, row = n >> 4, kgf = n & 15;
                el[v] = __ldg((const float4*)
                    (E + (((size_t)(b * Nv + (ii + 1) * 16 + (row >> 3)) * Nv)
                          + jb * 8 + (row & 7)) * FNv) + kgf);
            }
        }

        // ---- GEMM ----
        const uint32_t* __restrict__ Ew = (const uint32_t*)(sm + OFF_E16 + (ii & 1) * E16BUF);
        float c[2][8][4];
        #pragma unroll
        for (int mt = 0; mt < 2; mt++)
            #pragma unroll
            for (int nt = 0; nt < 8; nt++)
                #pragma unroll
                for (int q = 0; q < 4; q++) c[mt][nt][q] = 0.f;

        #pragma unroll
        for (int ks = 0; ks < 4; ks++) {
            uint32_t a[2][4];
            #pragma unroll
            for (int mt = 0; mt < 2; mt++) {
                const int r = mbase + mt * 16 + g;
                const uint2 u0 = *(const uint2*)(Ew + r * 40 + ks * 8 + tg * 2);
                const uint2 u1 = *(const uint2*)(Ew + (r + 8) * 40 + ks * 8 + tg * 2);
                a[mt][0] = u0.x; a[mt][1] = u1.x; a[mt][2] = u0.y; a[mt][3] = u1.y;
            }
            #pragma unroll
            for (int nt = 0; nt < 8; nt++) {
                mma16(c[0][nt], a[0], Breg[ks][nt].x, Breg[ks][nt].y);
                mma16(c[1][nt], a[1], Breg[ks][nt].x, Breg[ks][nt].y);
            }
        }

        // ---- epilogue: gate + i-accumulate (all rows share j = jb*8+g) ----
        const float*  __restrict__ As  = (const float*)(sm + OFF_A);
        const double* __restrict__ Pid = (const double*)(sm + OFF_PI);
        const double* __restrict__ Bsd = (const double*)(sm + OFF_BS);

        #pragma unroll
        for (int mt = 0; mt < 2; mt++) {
            #pragma unroll
            for (int h = 0; h < 2; h++) {
                const int il = wm * 4 + mt * 2 + h;
                const int i  = ii * 16 + il;
                const float ah = 0.5f * As[i * 8 + g];
                const double a2 = pack2d(ah, ah);
                const double* pir = Pid + (size_t)i * PIW;
                #pragma unroll
                for (int nt = 0; nt < 8; nt++) {
                    const int l = lbase + nt * 4 + tg;
                    const double d2 = pack2d(c[mt][nt][h * 2], c[mt][nt][h * 2 + 1]);
                    const double s2 = add2(add2(d2, pir[l]), pj2[nt]);
                    const float2 r  = unpack2d(fma2v(a2, s2, Bsd[l]));
                    float th; asm("tanh.approx.f32 %0, %1;" : "=f"(th) : "f"(r.x));
                    outacc[nt] = fmaf(fmaxf(r.y, 0.f), fmaf(0.5f, th, 0.5f), outacc[nt]);
                }
            }
        }
    }

    // ---- cross-warp (wm) reduction + store ----
    __syncthreads();
    float* __restrict__ Sred = (float*)(sm + OFF_E16);   // [wm][wn][g][32] = 2048 floats
    #pragma unroll
    for (int nt = 0; nt < 8; nt++)
        Sred[(((wm * 2 + wn) * 8 + g) * 32) + nt * 4 + tg] = outacc[nt];
    __syncthreads();

    {
        const int o = t * 2;                    // 512 outputs: j = o>>6, l = o&63
        const int j = o >> 6, l = o & 63;
        const int wnn = l >> 5, lloc = l & 31;
        float s0 = 0.f, s1 = 0.f;
        #pragma unroll
        for (int w = 0; w < 4; w++) {
            s0 += Sred[((w * 2 + wnn) * 8 + j) * 32 + lloc];
            s1 += Sred[((w * 2 + wnn) * 8 + j) * 32 + lloc + 1];
        }
        float2 v = make_float2(2.f * s0, 2.f * s1);       // undo pre-halving
        *(float2*)(out + ((size_t)(b * Nv) + jb * 8 + j) * FNv + l) = v;
    }
}

// ------------------------------ launch ------------------------------
extern "C" void kernel_launch(void* const* d_in, const int* in_sizes, int n_in,
                              void* d_out, int out_size) {
    const float* H    = (const float*)d_in[0];
    const float* A    = (const float*)d_in[1];
    const float* E    = (const float*)d_in[2];
    const float* Watt = (const float*)d_in[3];
    const float* Wnei = (const float*)d_in[4];
    const float* bAtt = (const float*)d_in[5];
    const float* bNei = (const float*)d_in[6];
    float* out = (float*)d_out;

    cudaFuncSetAttribute(main_kernel, cudaFuncAttributeMaxDynamicSharedMemorySize, SMEM_DYN);

    main_kernel<<<Bv * 16, 256, SMEM_DYN>>>(A, E, H, Watt, Wnei, bAtt, bNei, out);
}

// round 14
// speedup vs baseline: 1.2073x; 1.2073x over previous
#include <cuda_runtime.h>
#include <cuda_fp16.h>
#include <cstdint>
#include <cstddef>

#define Bv     8
#define Nv     128
#define FNv    64

// ------------------------------ helpers ------------------------------
__device__ __forceinline__ uint32_t smem_u32(const void* p) {
    uint32_t a;
    asm("{ .reg .u64 t; cvta.to.shared.u64 t, %1; cvt.u32.u64 %0, t; }" : "=r"(a) : "l"(p));
    return a;
}
__device__ __forceinline__ void cp16(uint32_t dst, const void* src) {
    asm volatile("cp.async.cg.shared.global [%0], [%1], 16;" :: "r"(dst), "l"(src) : "memory");
}
__device__ __forceinline__ void cp_commit() {
    asm volatile("cp.async.commit_group;" ::: "memory");
}
template <int N>
__device__ __forceinline__ void cp_wait() {
    asm volatile("cp.async.wait_group %0;" :: "n"(N) : "memory");
}
__device__ __forceinline__ uint32_t packh2(float lo, float hi) {
    uint32_t d; asm("cvt.rn.f16x2.f32 %0, %1, %2;" : "=r"(d) : "f"(hi), "f"(lo)); return d;
}
__device__ __forceinline__ void mma16(float* c, const uint32_t* a, uint32_t b0, uint32_t b1) {
    asm volatile(
        "mma.sync.aligned.m16n8k16.row.col.f32.f16.f16.f32 "
        "{%0,%1,%2,%3}, {%4,%5,%6,%7}, {%8,%9}, {%0,%1,%2,%3};"
        : "+f"(c[0]), "+f"(c[1]), "+f"(c[2]), "+f"(c[3])
        : "r"(a[0]), "r"(a[1]), "r"(a[2]), "r"(a[3]), "r"(b0), "r"(b1));
}
__device__ __forceinline__ double pack2d(float x, float y) {
    double r; asm("mov.b64 %0, {%1, %2};" : "=d"(r) : "f"(x), "f"(y)); return r;
}
__device__ __forceinline__ double add2(double a, double b) {
    double r; asm("add.rn.f32x2 %0, %1, %2;" : "=d"(r) : "d"(a), "d"(b)); return r;
}
__device__ __forceinline__ double fma2v(double a, double b, double c) {
    double r; asm("fma.rn.f32x2 %0, %1, %2, %3;" : "=d"(r) : "d"(a), "d"(b), "d"(c)); return r;
}
__device__ __forceinline__ float2 unpack2d(double v) {
    float2 f; asm("mov.b64 {%0, %1}, %2;" : "=f"(f.x), "=f"(f.y) : "d"(v)); return f;
}

// ------------------------------ main kernel ------------------------------
// CTA = (b, j-block of 8). 256 threads, 8 warps: wm = wid&3 (32 tile rows),
// wn = wid>>2 (64 n-cols = 32 l). Tile row r = il*8 + jl, i = ii*16+il, j = jb*8+jl.
// W smem: [n=2l+br (128)][kp halves (192 perm + pad16)] rows of 208 halves (104 words).
// ks 0..3 = We (W rows 128..191), ks 4..7 = Wj (64..127), ks 8..11 = Wi (0..63).
#define WROWH   208
#define OFF_W   0            // 128 x 416 B = 53248
#define OFF_E16 53248        // 2 x 20480 = 40960
#define E16BUF  20480
#define OFF_PI  94208        // 128 i x 66 float2 = 67584  (staging overlay pre-prologue)
#define PIW     66
#define OFF_PJ  161792       // 8 j x 66 float2 = 4224
#define PJW     66
#define OFF_A   166016       // 128 i x 8 j fp32 = 4096
#define OFF_BS  170112       // 64 float2 (pre-halved) = 512
#define SMEM_DYN 170624
#define SROWH   68           // staging row stride in halves (136 B, 8B-aligned)
#define SBR     13056        // staging per-matrix stride in halves (192*68)

__global__ void __launch_bounds__(256, 1)
main_kernel(const float* __restrict__ A,
            const float* __restrict__ E,
            const float* __restrict__ H,
            const float* __restrict__ Watt,
            const float* __restrict__ Wnei,
            const float* __restrict__ biasA,
            const float* __restrict__ biasN,
            float* __restrict__ out) {
    extern __shared__ char sm[];
    const uint32_t sb = smem_u32(sm);

    const int t = threadIdx.x, lane = t & 31, wid = t >> 5;
    const int g = lane >> 2, tg = lane & 3;
    const int b = blockIdx.x >> 4, jb = blockIdx.x & 15;
    const int wm = wid & 3;                     // m-quadrant
    const int wn = wid >> 2;                    // l-half
    const int mbase = wm * 32;
    const int lbase = wn * 32;
    const int nrow0 = wn * 64;

    const uint32_t* __restrict__ Ws = (const uint32_t*)(sm + OFF_W);

    // ---- A block via cp.async ----
    {
        const int ia = t >> 1, ha = t & 1;
        cp16(sb + OFF_A + ia * 32 + ha * 16,
             (const char*)(A + ((size_t)(b * Nv + ia)) * Nv + jb * 8) + ha * 16);
        cp_commit();
    }

    // ---- Phase A: W -> fp16 linear staging (coalesced LDG, conflict-free STS) ----
    {
        unsigned short* __restrict__ Sg = (unsigned short*)(sm + OFF_PI);
        #pragma unroll
        for (int v = 0; v < 24; v++) {
            const int gid4 = v * 256 + t;            // < 6144
            const int br = gid4 / 3072, rem = gid4 % 3072;
            const int row = rem >> 4, l4 = (rem & 15) * 4;
            const float* __restrict__ W = br ? Wnei : Watt;
            const float4 w4 = __ldg((const float4*)(W + row * 64 + l4));
            uint32_t* dst = (uint32_t*)(Sg + br * SBR + row * SROWH + l4);
            dst[0] = packh2(w4.x, w4.y);
            dst[1] = packh2(w4.z, w4.w);
        }
    }

    // ---- H tile: LDG -> fp16 permuted STS into E16 buf0 ----
    {
        const float4* Hg = (const float4*)(H + (size_t)b * Nv * FNv);
        float4 hl[8];
        #pragma unroll
        for (int v = 0; v < 8; v++) hl[v] = Hg[v * 256 + t];
        uint32_t* Ebw = (uint32_t*)(sm + OFF_E16);
        #pragma unroll
        for (int v = 0; v < 8; v++) {
            const int n = v * 256 + t, row = n >> 4, kgf = n & 15;
            const int wbase = row * 40 + (kgf >> 2) * 8 + ((kgf & 1) * 4) + ((kgf >> 1) & 1);
            Ebw[wbase]     = packh2(hl[v].x, hl[v].y);
            Ebw[wbase + 2] = packh2(hl[v].z, hl[v].w);
        }
    }
    if (t < 64)
        ((float2*)(sm + OFF_BS))[t] =
            make_float2(0.5f * __ldg(biasA + t), 0.5f * __ldg(biasN + t));
    cp_wait<0>();
    __syncthreads();          // staging + H-tile + A resident

    // ---- Phase B: build permuted W layout from staging ----
    {
        const unsigned short* __restrict__ Sg = (const unsigned short*)(sm + OFF_PI);
        unsigned short* __restrict__ Wh = (unsigned short*)(sm + OFF_W);
        #pragma unroll
        for (int v = 0; v < 6; v++) {
            const int pair = v * 256 + t;            // < 1536 = 128 n x 12 ks
            const int n = pair & 127, ks = pair >> 7;
            const int l = n >> 1, br = n & 1;
            const int rbase = (ks < 4) ? (128 + ks * 16)
                            : (ks < 8) ? (ks * 16)
                                       : ((ks - 8) * 16);
            const unsigned short* __restrict__ src = Sg + br * SBR + l;
            uint32_t u[8];
            #pragma unroll
            for (int q = 0; q < 8; q++) {
                const int p0 = 2 * q, p1 = 2 * q + 1;
                const int k0 = ((p0 >> 2) * 2) + (p0 & 1) + (((p0 >> 1) & 1) << 3);
                const int k1 = ((p1 >> 2) * 2) + (p1 & 1) + (((p1 >> 1) & 1) << 3);
                const uint32_t h0 = src[(rbase + k0) * SROWH];
                const uint32_t h1 = src[(rbase + k1) * SROWH];
                u[q] = h0 | (h1 << 16);
            }
            uint4* dst = (uint4*)(Wh + n * WROWH + ks * 16);
            dst[0] = make_uint4(u[0], u[1], u[2], u[3]);
            dst[1] = make_uint4(u[4], u[5], u[6], u[7]);
        }
    }
    __syncthreads();          // Wh visible (staging dead; PI area reusable below)

    // ---- prologue GEMM: Pi (ks 8..11, all 128 nodes) and Pj (ks 4..7, 8 nodes) ----
    {
        const uint32_t* __restrict__ Ew = (const uint32_t*)(sm + OFF_E16);
        float cpj[2][8][4], cpi[2][8][4];
        #pragma unroll
        for (int mt = 0; mt < 2; mt++)
            #pragma unroll
            for (int nt = 0; nt < 8; nt++)
                #pragma unroll
                for (int q = 0; q < 4; q++) { cpj[mt][nt][q] = 0.f; cpi[mt][nt][q] = 0.f; }

        #pragma unroll
        for (int ks = 0; ks < 4; ks++) {
            uint32_t a[2][4];
            #pragma unroll
            for (int mt = 0; mt < 2; mt++) {
                const int r = mbase + mt * 16 + g;
                const uint2 u0 = *(const uint2*)(Ew + r * 40 + ks * 8 + tg * 2);
                const uint2 u1 = *(const uint2*)(Ew + (r + 8) * 40 + ks * 8 + tg * 2);
                a[mt][0] = u0.x; a[mt][1] = u1.x; a[mt][2] = u0.y; a[mt][3] = u1.y;
            }
            #pragma unroll
            for (int nt = 0; nt < 8; nt++) {
                const int nr = (nrow0 + nt * 8 + g) * 104;
                const uint2 bj = *(const uint2*)(Ws + nr + (ks + 4) * 8 + tg * 2);
                const uint2 bi = *(const uint2*)(Ws + nr + (ks + 8) * 8 + tg * 2);
                mma16(cpj[0][nt], a[0], bj.x, bj.y);
                mma16(cpj[1][nt], a[1], bj.x, bj.y);
                mma16(cpi[0][nt], a[0], bi.x, bi.y);
                mma16(cpi[1][nt], a[1], bi.x, bi.y);
            }
        }
        // scatter Pi (all 128 rows)
        float2* __restrict__ PIs = (float2*)(sm + OFF_PI);
        #pragma unroll
        for (int mt = 0; mt < 2; mt++) {
            const int r0 = mbase + mt * 16 + g;
            #pragma unroll
            for (int nt = 0; nt < 8; nt++) {
                const int l = lbase + nt * 4 + tg;
                PIs[(size_t)r0 * PIW + l]       = make_float2(cpi[mt][nt][0], cpi[mt][nt][1]);
                PIs[(size_t)(r0 + 8) * PIW + l] = make_float2(cpi[mt][nt][2], cpi[mt][nt][3]);
            }
        }
        // scatter Pj window (rows jb*8 .. +8): owning (wm, mt, h) combo
        float2* __restrict__ PJs = (float2*)(sm + OFF_PJ);
        #pragma unroll
        for (int mt = 0; mt < 2; mt++) {
            #pragma unroll
            for (int h = 0; h < 2; h++) {
                if (wm * 4 + mt * 2 + h == jb) {
                    #pragma unroll
                    for (int nt = 0; nt < 8; nt++) {
                        const int l = lbase + nt * 4 + tg;
                        const float va = cpj[mt][nt][h * 2];
                        const float vn = cpj[mt][nt][h * 2 + 1];
                        PJs[(size_t)g * PJW + l] = make_float2(va, vn);
                    }
                }
            }
        }
    }

    // ---- hoist B fragments (We, ks 0..3) into registers ----
    uint2 Breg[4][8];
    #pragma unroll
    for (int ks = 0; ks < 4; ks++)
        #pragma unroll
        for (int nt = 0; nt < 8; nt++)
            Breg[ks][nt] = *(const uint2*)(Ws + (nrow0 + nt * 8 + g) * 104 + ks * 8 + tg * 2);

    // ---- prefetch E tile 0 (rows r = il*8+jl, i = r>>3, j = jb*8 + (r&7)) ----
    float4 el[8];
    {
        #pragma unroll
        for (int v = 0; v < 8; v++) {
            const int n = v * 256 + t, row = n >> 4, kgf = n & 15;
            el[v] = __ldg((const float4*)
                (E + (((size_t)(b * Nv + (row >> 3)) * Nv) + jb * 8 + (row & 7)) * FNv) + kgf);
        }
    }
    __syncthreads();          // Pi/Pj visible; H reads done -> buf0 reusable

    // ---- Pj into registers (j = jb*8+g fixed per thread) ----
    double pj2[8];
    {
        const double* __restrict__ PJd = (const double*)(sm + OFF_PJ);
        #pragma unroll
        for (int nt = 0; nt < 8; nt++)
            pj2[nt] = PJd[(size_t)g * PJW + lbase + nt * 4 + tg];
    }

    float outacc[8];
    #pragma unroll
    for (int nt = 0; nt < 8; nt++) outacc[nt] = 0.f;

    for (int ii = 0; ii < 8; ii++) {
        // ---- convert + store tile ii ----
        {
            uint32_t* Ebw = (uint32_t*)(sm + OFF_E16 + (ii & 1) * E16BUF);
            #pragma unroll
            for (int v = 0; v < 8; v++) {
                const int n = v * 256 + t, row = n >> 4, kgf = n & 15;
                const int wbase = row * 40 + (kgf >> 2) * 8 + ((kgf & 1) * 4) + ((kgf >> 1) & 1);
                Ebw[wbase]     = packh2(el[v].x, el[v].y);
                Ebw[wbase + 2] = packh2(el[v].z, el[v].w);
            }
        }
        __syncthreads();

        // ---- prefetch tile ii+1 ----
        if (ii + 1 < 8) {
            #pragma unroll
            for (int v = 0; v < 8; v++) {
                const int n = v * 256 + t, row = n >> 4, kgf = n & 15;
                el[v] = __ldg((const float4*)
                    (E + (((size_t)(b * Nv + (ii + 1) * 16 + (row >> 3)) * Nv)
                          + jb * 8 + (row & 7)) * FNv) + kgf);
            }
        }

        // ---- GEMM ----
        const uint32_t* __restrict__ Ew = (const uint32_t*)(sm + OFF_E16 + (ii & 1) * E16BUF);
        float c[2][8][4];
        #pragma unroll
        for (int mt = 0; mt < 2; mt++)
            #pragma unroll
            for (int nt = 0; nt < 8; nt++)
                #pragma unroll
                for (int q = 0; q < 4; q++) c[mt][nt][q] = 0.f;

        #pragma unroll
        for (int ks = 0; ks < 4; ks++) {
            uint32_t a[2][4];
            #pragma unroll
            for (int mt = 0; mt < 2; mt++) {
                const int r = mbase + mt * 16 + g;
                const uint2 u0 = *(const uint2*)(Ew + r * 40 + ks * 8 + tg * 2);
                const uint2 u1 = *(const uint2*)(Ew + (r + 8) * 40 + ks * 8 + tg * 2);
                a[mt][0] = u0.x; a[mt][1] = u1.x; a[mt][2] = u0.y; a[mt][3] = u1.y;
            }
            #pragma unroll
            for (int nt = 0; nt < 8; nt++) {
                mma16(c[0][nt], a[0], Breg[ks][nt].x, Breg[ks][nt].y);
                mma16(c[1][nt], a[1], Breg[ks][nt].x, Breg[ks][nt].y);
            }
        }

        // ---- epilogue: gate + i-accumulate (all rows share j = jb*8+g) ----
        const float*  __restrict__ As  = (const float*)(sm + OFF_A);
        const double* __restrict__ Pid = (const double*)(sm + OFF_PI);
        const double* __restrict__ Bsd = (const double*)(sm + OFF_BS);

        #pragma unroll
        for (int mt = 0; mt < 2; mt++) {
            #pragma unroll
            for (int h = 0; h < 2; h++) {
                const int il = wm * 4 + mt * 2 + h;
                const int i  = ii * 16 + il;
                const float ah = 0.5f * As[i * 8 + g];
                const double a2 = pack2d(ah, ah);
                const double* pir = Pid + (size_t)i * PIW;
                #pragma unroll
                for (int nt = 0; nt < 8; nt++) {
                    const int l = lbase + nt * 4 + tg;
                    const double d2 = pack2d(c[mt][nt][h * 2], c[mt][nt][h * 2 + 1]);
                    const double s2 = add2(add2(d2, pir[l]), pj2[nt]);
                    const float2 r  = unpack2d(fma2v(a2, s2, Bsd[l]));
                    float th; asm("tanh.approx.f32 %0, %1;" : "=f"(th) : "f"(r.x));
                    outacc[nt] = fmaf(fmaxf(r.y, 0.f), fmaf(0.5f, th, 0.5f), outacc[nt]);
                }
            }
        }
    }

    // ---- cross-warp (wm) reduction + store ----
    __syncthreads();
    float* __restrict__ Sred = (float*)(sm + OFF_E16);   // [wm][wn][g][32] = 2048 floats
    #pragma unroll
    for (int nt = 0; nt < 8; nt++)
        Sred[(((wm * 2 + wn) * 8 + g) * 32) + nt * 4 + tg] = outacc[nt];
    __syncthreads();

    {
        const int o = t * 2;                    // 512 outputs: j = o>>6, l = o&63
        const int j = o >> 6, l = o & 63;
        const int wnn = l >> 5, lloc = l & 31;
        float s0 = 0.f, s1 = 0.f;
        #pragma unroll
        for (int w = 0; w < 4; w++) {
            s0 += Sred[((w * 2 + wnn) * 8 + j) * 32 + lloc];
            s1 += Sred[((w * 2 + wnn) * 8 + j) * 32 + lloc + 1];
        }
        float2 v = make_float2(2.f * s0, 2.f * s1);       // undo pre-halving
        *(float2*)(out + ((size_t)(b * Nv) + jb * 8 + j) * FNv + l) = v;
    }
}

// ------------------------------ launch ------------------------------
extern "C" void kernel_launch(void* const* d_in, const int* in_sizes, int n_in,
                              void* d_out, int out_size) {
    const float* H    = (const float*)d_in[0];
    const float* A    = (const float*)d_in[1];
    const float* E    = (const float*)d_in[2];
    const float* Watt = (const float*)d_in[3];
    const float* Wnei = (const float*)d_in[4];
    const float* bAtt = (const float*)d_in[5];
    const float* bNei = (const float*)d_in[6];
    float* out = (float*)d_out;

    cudaFuncSetAttribute(main_kernel, cudaFuncAttributeMaxDynamicSharedMemorySize, SMEM_DYN);

    main_kernel<<<Bv * 16, 256, SMEM_DYN>>>(A, E, H, Watt, Wnei, bAtt, bNei, out);
}